// round 15
// baseline (speedup 1.0000x reference)
#include <cuda_runtime.h>
#include <cuda_fp16.h>
#include <cstddef>
#include <cstdint>

#define NN 40000
#define EE 640000
#define GG 1000
#define HC 128
#define NH 8
#define CC 16
#define MM 256

// ---------------- scratch (static device globals; no allocation) ----------------
__device__ __half  g_x16[NN * 32];    // fp16 copy of input x
__device__ __half2 g_h16[NN * 64];    // fp16 pre-agg features (gather source)
__device__ __half2 g_fA16[NN * 64];   // fp16 post-agg features (ping)
__device__ __half2 g_fB16[NN * 64];   // fp16 post-agg features (pong)
__device__ float g_als[NN * NH];
__device__ float g_ald[NN * NH];
__device__ int   g_deg[NN];
__device__ int   g_cur[NN];
__device__ int   g_off[NN + 1];
__device__ int   g_csr[EE];

__device__ __forceinline__ float lrelu(float x) { return fmaxf(x, 0.2f * x); }

__device__ __forceinline__ uint32_t smem_u32(const void* p) {
    uint32_t a;
    asm("{ .reg .u64 t; cvta.to.shared.u64 t, %1; cvt.u32.u64 %0, t; }"
        : "=r"(a) : "l"(p));
    return a;
}

__device__ __forceinline__ void cpasync16(uint32_t s, const void* g) {
    asm volatile("cp.async.ca.shared.global [%0], [%1], 16;" :: "r"(s), "l"(g));
}

// ---- packed f32x2 ----
__device__ __forceinline__ uint64_t pk2(float lo, float hi) {
    uint64_t r;
    asm("mov.b64 %0, {%1, %2};" : "=l"(r) : "f"(lo), "f"(hi));
    return r;
}
__device__ __forceinline__ void fma2(uint64_t& c, uint64_t a, uint64_t b) {
    asm("fma.rn.f32x2 %0, %1, %2, %0;" : "+l"(c) : "l"(a), "l"(b));
}
__device__ __forceinline__ float2 unpk2(uint64_t v) {
    float2 r;
    asm("mov.b64 {%0, %1}, %2;" : "=f"(r.x), "=f"(r.y) : "l"(v));
    return r;
}

// ---------------- fused hist + x->fp16 (both exactly EE = NN*16 items) --------
__global__ void k_hist_cvtx(const int* __restrict__ dst, const float* __restrict__ x,
                            __half* __restrict__ xh) {
    int i = blockIdx.x * blockDim.x + threadIdx.x;
    if (i < EE) atomicAdd(&g_deg[dst[i]], 1);
    if (i < NN * 16) {
        float2 v = *(const float2*)(x + (size_t)i * 2);
        __half2 h = __floats2half2_rn(v.x, v.y);
        *(__half2*)(xh + (size_t)i * 2) = h;
    }
}

__global__ void k_scan() {
    const int ITEMS = 40;
    int t = threadIdx.x;
    int base = t * ITEMS;
    int sum = 0;
    for (int i = 0; i < ITEMS; i++) {
        int idx = base + i;
        if (idx < NN) sum += g_deg[idx];
    }
    __shared__ int wsum[32];
    int lane = t & 31, wid = t >> 5;
    int v = sum;
    #pragma unroll
    for (int o = 1; o < 32; o <<= 1) {
        int u = __shfl_up_sync(0xffffffffu, v, o);
        if (lane >= o) v += u;
    }
    if (lane == 31) wsum[wid] = v;
    __syncthreads();
    if (wid == 0) {
        int w = wsum[lane];
        #pragma unroll
        for (int o = 1; o < 32; o <<= 1) {
            int u = __shfl_up_sync(0xffffffffu, w, o);
            if (lane >= o) w += u;
        }
        wsum[lane] = w;
    }
    __syncthreads();
    int excl = v - sum + (wid > 0 ? wsum[wid - 1] : 0);
    int run = excl;
    for (int i = 0; i < ITEMS; i++) {
        int idx = base + i;
        if (idx < NN) { g_off[idx] = run; g_cur[idx] = run; run += g_deg[idx]; }
    }
    if (t == 1023) g_off[NN] = EE;
}

// ---------------- fp16 HMMA GEMM body + fused logits (device fn) ----------------
template <int K>
__device__ void gemm_body(const __half* __restrict__ in, const float* __restrict__ W,
                          __half2* __restrict__ h16, const float* __restrict__ as_,
                          const float* __restrict__ ad_, int blk) {
    constexpr int CH = K / 32;
    __shared__ __half As[2][128][40];
    __shared__ __half Ws[2][32][136];

    int t = threadIdx.x;
    int lane = t & 31;
    int warp = t >> 5;
    int warpM = warp & 1;
    int warpN = warp >> 1;
    int row0 = blk * 128;

    float acc[4][4][4];
    #pragma unroll
    for (int mt = 0; mt < 4; mt++)
        #pragma unroll
        for (int nt = 0; nt < 4; nt++)
            #pragma unroll
            for (int r = 0; r < 4; r++) acc[mt][nt][r] = 0.f;

    float4 wreg[4];

    {
        #pragma unroll
        for (int j = 0; j < 2; j++) {
            int slot = t + j * 256;
            int r = slot >> 2, k8 = (slot & 3) * 8;
            int rg = row0 + r; if (rg >= NN) rg = NN - 1;
            cpasync16(smem_u32(&As[0][r][k8]), in + (size_t)rg * K + k8);
        }
        #pragma unroll
        for (int j = 0; j < 4; j++) {
            int slot = t + j * 256;
            int kk = slot >> 5, c4 = (slot & 31) * 4;
            float4 v = *(const float4*)(W + (size_t)kk * 128 + c4);
            __half2 h0 = __floats2half2_rn(v.x, v.y);
            __half2 h1 = __floats2half2_rn(v.z, v.w);
            uint2 p = {*(uint32_t*)&h0, *(uint32_t*)&h1};
            *(uint2*)&Ws[0][kk][c4] = p;
        }
        asm volatile("cp.async.commit_group;");
        asm volatile("cp.async.wait_group 0;");
        __syncthreads();
    }

    for (int c = 0; c < CH; c++) {
        int cur = c & 1, nxt = cur ^ 1;
        bool more = (c + 1 < CH);
        if (more) {
            int k0 = (c + 1) * 32;
            #pragma unroll
            for (int j = 0; j < 2; j++) {
                int slot = t + j * 256;
                int r = slot >> 2, k8 = (slot & 3) * 8;
                int rg = row0 + r; if (rg >= NN) rg = NN - 1;
                cpasync16(smem_u32(&As[nxt][r][k8]), in + (size_t)rg * K + k0 + k8);
            }
            asm volatile("cp.async.commit_group;");
            #pragma unroll
            for (int j = 0; j < 4; j++) {
                int slot = t + j * 256;
                int kk = slot >> 5, c4 = (slot & 31) * 4;
                wreg[j] = *(const float4*)(W + (size_t)(k0 + kk) * 128 + c4);
            }
        }

        #pragma unroll
        for (int ks = 0; ks < 2; ks++) {
            uint32_t a[4][4], b[4][2];
            #pragma unroll
            for (int mt = 0; mt < 4; mt++) {
                int r = warpM * 64 + mt * 16 + (lane & 15);
                uint32_t addr = smem_u32(&As[cur][r][ks * 16 + ((lane >> 4) * 8)]);
                asm volatile("ldmatrix.sync.aligned.m8n8.x4.shared.b16 {%0,%1,%2,%3}, [%4];"
                    : "=r"(a[mt][0]), "=r"(a[mt][1]), "=r"(a[mt][2]), "=r"(a[mt][3])
                    : "r"(addr));
            }
            #pragma unroll
            for (int nt = 0; nt < 4; nt++) {
                int kk = ks * 16 + (lane & 15);
                uint32_t addr = smem_u32(&Ws[cur][kk][warpN * 32 + nt * 8]);
                asm volatile("ldmatrix.sync.aligned.m8n8.x2.trans.shared.b16 {%0,%1}, [%2];"
                    : "=r"(b[nt][0]), "=r"(b[nt][1]) : "r"(addr));
            }
            #pragma unroll
            for (int mt = 0; mt < 4; mt++)
                #pragma unroll
                for (int nt = 0; nt < 4; nt++)
                    asm volatile(
                        "mma.sync.aligned.m16n8k16.row.col.f32.f16.f16.f32 "
                        "{%0,%1,%2,%3}, {%4,%5,%6,%7}, {%8,%9}, {%0,%1,%2,%3};"
                        : "+f"(acc[mt][nt][0]), "+f"(acc[mt][nt][1]),
                          "+f"(acc[mt][nt][2]), "+f"(acc[mt][nt][3])
                        : "r"(a[mt][0]), "r"(a[mt][1]), "r"(a[mt][2]), "r"(a[mt][3]),
                          "r"(b[nt][0]), "r"(b[nt][1]));
        }

        if (more) {
            #pragma unroll
            for (int j = 0; j < 4; j++) {
                int slot = t + j * 256;
                int kk = slot >> 5, c4 = (slot & 31) * 4;
                __half2 h0 = __floats2half2_rn(wreg[j].x, wreg[j].y);
                __half2 h1 = __floats2half2_rn(wreg[j].z, wreg[j].w);
                uint2 p = {*(uint32_t*)&h0, *(uint32_t*)&h1};
                *(uint2*)&Ws[nxt][kk][c4] = p;
            }
            asm volatile("cp.async.wait_group 0;");
        }
        __syncthreads();
    }

    // ---- epilogue: fp16 h store + fused fp32 logits ----
    int hbase = warpN * 2;
    float asv[4][2], adv[4][2];
    #pragma unroll
    for (int nt = 0; nt < 4; nt++) {
        int col = warpN * 32 + nt * 8 + (lane & 3) * 2;
        int hh = col >> 4;
        int lc = col & 15;
        asv[nt][0] = __ldg(as_ + hh * 16 + lc);
        asv[nt][1] = __ldg(as_ + hh * 16 + lc + 1);
        adv[nt][0] = __ldg(ad_ + hh * 16 + lc);
        adv[nt][1] = __ldg(ad_ + hh * 16 + lc + 1);
    }
    #pragma unroll
    for (int mt = 0; mt < 4; mt++) {
        int r0 = row0 + warpM * 64 + mt * 16 + (lane >> 2);
        float sA[2] = {0.f, 0.f}, dA[2] = {0.f, 0.f};
        float sB[2] = {0.f, 0.f}, dB[2] = {0.f, 0.f};
        #pragma unroll
        for (int nt = 0; nt < 4; nt++) {
            int hs = nt >> 1;
            sA[hs] += acc[mt][nt][0] * asv[nt][0] + acc[mt][nt][1] * asv[nt][1];
            dA[hs] += acc[mt][nt][0] * adv[nt][0] + acc[mt][nt][1] * adv[nt][1];
            sB[hs] += acc[mt][nt][2] * asv[nt][0] + acc[mt][nt][3] * asv[nt][1];
            dB[hs] += acc[mt][nt][2] * adv[nt][0] + acc[mt][nt][3] * adv[nt][1];
            __half2 hv0 = __floats2half2_rn(acc[mt][nt][0], acc[mt][nt][1]);
            __half2 hv1 = __floats2half2_rn(acc[mt][nt][2], acc[mt][nt][3]);
            int colh = warpN * 16 + nt * 4 + (lane & 3);
            if (r0 < NN)     h16[(size_t)r0 * 64 + colh] = hv0;
            if (r0 + 8 < NN) h16[(size_t)(r0 + 8) * 64 + colh] = hv1;
        }
        #pragma unroll
        for (int h = 0; h < 2; h++) {
            #pragma unroll
            for (int o = 1; o <= 2; o <<= 1) {
                sA[h] += __shfl_xor_sync(0xffffffffu, sA[h], o);
                dA[h] += __shfl_xor_sync(0xffffffffu, dA[h], o);
                sB[h] += __shfl_xor_sync(0xffffffffu, sB[h], o);
                dB[h] += __shfl_xor_sync(0xffffffffu, dB[h], o);
            }
        }
        if ((lane & 3) == 0) {
            #pragma unroll
            for (int h = 0; h < 2; h++) {
                if (r0 < NN) {
                    g_als[r0 * NH + hbase + h] = sA[h];
                    g_ald[r0 * NH + hbase + h] = dA[h];
                }
                if (r0 + 8 < NN) {
                    g_als[(r0 + 8) * NH + hbase + h] = sB[h];
                    g_ald[(r0 + 8) * NH + hbase + h] = dB[h];
                }
            }
        }
    }
}

template <int K>
__global__ void __launch_bounds__(256) k_gemm_h(const __half* __restrict__ in,
                                                const float* __restrict__ W,
                                                __half2* __restrict__ h16,
                                                const float* __restrict__ as_,
                                                const float* __restrict__ ad_) {
    gemm_body<K>(in, W, h16, as_, ad_, blockIdx.x);
}

// gemm<32> for blocks 0..312, CSR fill for blocks 313..2812 (one launch)
__global__ void __launch_bounds__(256) k_gemm_fill(const __half* __restrict__ in,
                                                   const float* __restrict__ W,
                                                   __half2* __restrict__ h16,
                                                   const float* __restrict__ as_,
                                                   const float* __restrict__ ad_,
                                                   const int* __restrict__ src,
                                                   const int* __restrict__ dst) {
    if (blockIdx.x < 313) {
        gemm_body<32>(in, W, h16, as_, ad_, blockIdx.x);
    } else {
        int i = (blockIdx.x - 313) * blockDim.x + threadIdx.x;
        if (i < EE) {
            int p = atomicAdd(&g_cur[dst[i]], 1);
            g_csr[p] = src[i];
        }
    }
}

// ---------------- agg: single-sweep softmax (no max-shift), instr-trimmed -------
__global__ void k_agg(const __half2* __restrict__ h, const float* __restrict__ bias,
                      __half2* __restrict__ outf) {
    int warp = (blockIdx.x * blockDim.x + threadIdx.x) >> 5;
    if (warp >= NN) return;
    int lane = threadIdx.x & 31;
    int node = warp;
    int beg = g_off[node], end = g_off[node + 1];
    int head3 = lane >> 2;
    float aldh = g_ald[node * NH + head3];
    const __half2* hp = h + lane * 2;          // hoisted per-lane base

    float4 acc;
    float d0, d1 = 0.f;
    {
        float w = __expf(lrelu(g_als[node * NH + head3] + aldh));
        uint2 raw = *(const uint2*)(hp + (size_t)node * 64);
        float2 c0 = __half22float2(*(__half2*)&raw.x);
        float2 c1 = __half22float2(*(__half2*)&raw.y);
        acc.x = w * c0.x; acc.y = w * c0.y; acc.z = w * c1.x; acc.w = w * c1.y;
        d0 = w;
    }
    int e = beg;
    for (; e + 3 < end; e += 4) {
        int s0 = g_csr[e], s1 = g_csr[e + 1], s2 = g_csr[e + 2], s3 = g_csr[e + 3];
        float l0 = g_als[s0 * NH + head3];
        float l1 = g_als[s1 * NH + head3];
        float l2 = g_als[s2 * NH + head3];
        float l3 = g_als[s3 * NH + head3];
        uint2 r0 = *(const uint2*)(hp + (size_t)s0 * 64);
        uint2 r1 = *(const uint2*)(hp + (size_t)s1 * 64);
        uint2 r2 = *(const uint2*)(hp + (size_t)s2 * 64);
        uint2 r3 = *(const uint2*)(hp + (size_t)s3 * 64);
        float w0 = __expf(lrelu(l0 + aldh));
        float w1 = __expf(lrelu(l1 + aldh));
        float w2 = __expf(lrelu(l2 + aldh));
        float w3 = __expf(lrelu(l3 + aldh));
        d0 += w0 + w1;
        d1 += w2 + w3;
        float2 h00 = __half22float2(*(__half2*)&r0.x);
        float2 h01 = __half22float2(*(__half2*)&r0.y);
        float2 h10 = __half22float2(*(__half2*)&r1.x);
        float2 h11 = __half22float2(*(__half2*)&r1.y);
        float2 h20 = __half22float2(*(__half2*)&r2.x);
        float2 h21 = __half22float2(*(__half2*)&r2.y);
        float2 h30 = __half22float2(*(__half2*)&r3.x);
        float2 h31 = __half22float2(*(__half2*)&r3.y);
        acc.x += w0 * h00.x + w1 * h10.x + w2 * h20.x + w3 * h30.x;
        acc.y += w0 * h00.y + w1 * h10.y + w2 * h20.y + w3 * h30.y;
        acc.z += w0 * h01.x + w1 * h11.x + w2 * h21.x + w3 * h31.x;
        acc.w += w0 * h01.y + w1 * h11.y + w2 * h21.y + w3 * h31.y;
    }
    for (; e < end; e++) {
        int s0 = g_csr[e];
        float w = __expf(lrelu(g_als[s0 * NH + head3] + aldh));
        uint2 raw = *(const uint2*)(hp + (size_t)s0 * 64);
        float2 c0 = __half22float2(*(__half2*)&raw.x);
        float2 c1 = __half22float2(*(__half2*)&raw.y);
        d0 += w;
        acc.x += w * c0.x; acc.y += w * c0.y; acc.z += w * c1.x; acc.w += w * c1.y;
    }
    float inv = 1.f / (d0 + d1);
    float4 bv = *(const float4*)(bias + lane * 4);
    float ox = fmaxf(acc.x * inv + bv.x, 0.f);
    float oy = fmaxf(acc.y * inv + bv.y, 0.f);
    float oz = fmaxf(acc.z * inv + bv.z, 0.f);
    float ow = fmaxf(acc.w * inv + bv.w, 0.f);
    __half2 q0 = __floats2half2_rn(ox, oy);
    __half2 q1 = __floats2half2_rn(oz, ow);
    uint2 st = {*(uint32_t*)&q0, *(uint32_t*)&q1};
    *(uint2*)(outf + (size_t)node * 64 + lane * 2) = st;
}

// ---------------- fused tail: pool + fc128 + fc256 + head (block = 8 graphs) ----
__device__ __forceinline__ int lower_bound_i(const int* __restrict__ a, int n, int key) {
    int lo = 0, hi = n;
    while (lo < hi) {
        int mid = (lo + hi) >> 1;
        if (a[mid] < key) lo = mid + 1; else hi = mid;
    }
    return lo;
}

__global__ void __launch_bounds__(256) k_tail(const __half2* __restrict__ feat,
                                              const int* __restrict__ batch,
                                              const float* __restrict__ fW0,
                                              const float* __restrict__ fb0,
                                              const float* __restrict__ fW1,
                                              const float* __restrict__ fb1,
                                              const float* __restrict__ oW,
                                              const float* __restrict__ ob,
                                              float* __restrict__ out) {
    __shared__ float2 spool[4][HC];    // graph pair j holds graphs (2j, 2j+1)
    __shared__ float2 sm0[4][MM];
    __shared__ float2 sm1[4][MM];
    int t = threadIdx.x;
    int warp = t >> 5, lane = t & 31;
    int gblk = blockIdx.x * 8;

    // pool: warp per graph
    {
        int g = gblk + warp;
        int start = lower_bound_i(batch, NN, g);
        int end = lower_bound_i(batch, NN, g + 1);
        float4 acc = {0.f, 0.f, 0.f, 0.f};
        for (int n = start; n < end; n++) {
            uint2 raw = *(const uint2*)(feat + (size_t)n * 64 + lane * 2);
            float2 c0 = __half22float2(*(__half2*)&raw.x);
            float2 c1 = __half22float2(*(__half2*)&raw.y);
            acc.x += c0.x; acc.y += c0.y; acc.z += c1.x; acc.w += c1.y;
        }
        float invc = (end > start) ? 1.f / (float)(end - start) : 0.f;
        int p = warp >> 1, s = warp & 1;
        ((float*)&spool[p][lane * 4 + 0])[s] = acc.x * invc;
        ((float*)&spool[p][lane * 4 + 1])[s] = acc.y * invc;
        ((float*)&spool[p][lane * 4 + 2])[s] = acc.z * invc;
        ((float*)&spool[p][lane * 4 + 3])[s] = acc.w * invc;
    }
    __syncthreads();

    // fc1: K=128 -> 256, t = output channel
    {
        uint64_t a[4] = {0ull, 0ull, 0ull, 0ull};
        for (int k = 0; k < HC; k++) {
            float w = fW0[(size_t)k * MM + t];
            uint64_t w2 = pk2(w, w);
            #pragma unroll
            for (int j = 0; j < 4; j++) fma2(a[j], w2, *(const uint64_t*)&spool[j][k]);
        }
        float bb = fb0[t];
        #pragma unroll
        for (int j = 0; j < 4; j++) {
            float2 p = unpk2(a[j]);
            sm0[j][t] = make_float2(fmaxf(p.x + bb, 0.f), fmaxf(p.y + bb, 0.f));
        }
    }
    __syncthreads();

    // fc2: K=256 -> 256
    {
        uint64_t a[4] = {0ull, 0ull, 0ull, 0ull};
        for (int k = 0; k < MM; k++) {
            float w = fW1[(size_t)k * MM + t];
            uint64_t w2 = pk2(w, w);
            #pragma unroll
            for (int j = 0; j < 4; j++) fma2(a[j], w2, *(const uint64_t*)&sm0[j][k]);
        }
        float bb = fb1[t];
        #pragma unroll
        for (int j = 0; j < 4; j++) {
            float2 p = unpk2(a[j]);
            sm1[j][t] = make_float2(fmaxf(p.x + bb, 0.f), fmaxf(p.y + bb, 0.f));
        }
    }
    __syncthreads();

    // head: warp per graph
    {
        int g = gblk + warp;
        int p = warp >> 1, s = warp & 1;
        float a0 = 0.f, a1 = 0.f;
        for (int k = lane; k < MM; k += 32) {
            float v = ((const float*)&sm1[p][k])[s];
            a0 += v * oW[k * 2];
            a1 += v * oW[k * 2 + 1];
        }
        #pragma unroll
        for (int o = 16; o > 0; o >>= 1) {
            a0 += __shfl_xor_sync(0xffffffffu, a0, o);
            a1 += __shfl_xor_sync(0xffffffffu, a1, o);
        }
        if (lane == 0) {
            out[g * 2] = a0 + ob[0];
            out[g * 2 + 1] = a1 + ob[1];
        }
    }
}

// ---------------- launch ----------------
extern "C" void kernel_launch(void* const* d_in, const int* in_sizes, int n_in,
                              void* d_out, int out_size) {
    const float* x     = (const float*)d_in[0];
    const int*   ei    = (const int*)d_in[1];
    const int*   batch = (const int*)d_in[2];
    const float* W0  = (const float*)d_in[3];
    const float* b0  = (const float*)d_in[4];
    const float* as0 = (const float*)d_in[5];
    const float* ad0 = (const float*)d_in[6];
    const float* W1  = (const float*)d_in[7];
    const float* b1  = (const float*)d_in[8];
    const float* as1 = (const float*)d_in[9];
    const float* ad1 = (const float*)d_in[10];
    const float* W2  = (const float*)d_in[11];
    const float* b2  = (const float*)d_in[12];
    const float* as2 = (const float*)d_in[13];
    const float* ad2 = (const float*)d_in[14];
    const float* fW0 = (const float*)d_in[15];
    const float* fb0 = (const float*)d_in[16];
    const float* fW1 = (const float*)d_in[17];
    const float* fb1 = (const float*)d_in[18];
    const float* oW  = (const float*)d_in[19];
    const float* ob  = (const float*)d_in[20];
    float* out = (float*)d_out;

    const int* src = ei;
    const int* dst = ei + EE;

    __half* p_x16;
    __half2 *p_h16, *p_fA, *p_fB;
    cudaGetSymbolAddress((void**)&p_x16, g_x16);
    cudaGetSymbolAddress((void**)&p_h16, g_h16);
    cudaGetSymbolAddress((void**)&p_fA, g_fA16);
    cudaGetSymbolAddress((void**)&p_fB, g_fB16);
    int* p_deg;
    cudaGetSymbolAddress((void**)&p_deg, g_deg);

    const int GEMM_GRID = (NN + 127) / 128;   // 313
    const int AGG_GRID = (NN + 7) / 8;

    cudaMemsetAsync(p_deg, 0, NN * sizeof(int));

    // launch 1: hist + x->fp16
    k_hist_cvtx<<<(EE + 255) / 256, 256>>>(dst, x, p_x16);
    // launch 2: scan (off + cur)
    k_scan<<<1, 1024>>>();
    // launch 3: gemm<32> + CSR fill
    k_gemm_fill<<<313 + (EE + 255) / 256, 256>>>(p_x16, W0, p_h16, as0, ad0, src, dst);
    // launch 4 (PROFILED): layer-0 agg
    k_agg<<<AGG_GRID, 256>>>(p_h16, b0, p_fA);
    // layer 1
    k_gemm_h<128><<<GEMM_GRID, 256>>>((const __half*)p_fA, W1, p_h16, as1, ad1);
    k_agg<<<AGG_GRID, 256>>>(p_h16, b1, p_fB);
    // layer 2
    k_gemm_h<128><<<GEMM_GRID, 256>>>((const __half*)p_fB, W2, p_h16, as2, ad2);
    k_agg<<<AGG_GRID, 256>>>(p_h16, b2, p_fA);

    // fused tail: pool + fc + fc + head
    k_tail<<<GG / 8, 256>>>(p_fA, batch, fW0, fb0, fW1, fb1, oW, ob, out);
}

// round 16
// speedup vs baseline: 1.5737x; 1.5737x over previous
#include <cuda_runtime.h>
#include <cuda_fp16.h>
#include <cstddef>
#include <cstdint>

#define NN 40000
#define EE 640000
#define GG 1000
#define HC 128
#define NH 8
#define CC 16
#define MM 256

// ---------------- scratch (static device globals; no allocation) ----------------
__device__ __half  g_x16[NN * 32];    // fp16 copy of input x
__device__ __half2 g_h16[NN * 64];    // fp16 pre-agg features (gather source)
__device__ __half2 g_fA16[NN * 64];   // fp16 post-agg features (ping)
__device__ __half2 g_fB16[NN * 64];   // fp16 post-agg features (pong)
__device__ float g_als[NN * NH];
__device__ float g_ald[NN * NH];
__device__ int   g_deg[NN];
__device__ int   g_cur[NN];
__device__ int   g_off[NN + 1];
__device__ int   g_csr[EE];

__device__ __forceinline__ float lrelu(float x) { return x > 0.f ? x : 0.2f * x; }

__device__ __forceinline__ uint32_t smem_u32(const void* p) {
    uint32_t a;
    asm("{ .reg .u64 t; cvta.to.shared.u64 t, %1; cvt.u32.u64 %0, t; }"
        : "=r"(a) : "l"(p));
    return a;
}

__device__ __forceinline__ void cpasync16(uint32_t s, const void* g) {
    asm volatile("cp.async.ca.shared.global [%0], [%1], 16;" :: "r"(s), "l"(g));
}

// ---- packed f32x2 ----
__device__ __forceinline__ uint64_t pk2(float lo, float hi) {
    uint64_t r;
    asm("mov.b64 %0, {%1, %2};" : "=l"(r) : "f"(lo), "f"(hi));
    return r;
}
__device__ __forceinline__ void fma2(uint64_t& c, uint64_t a, uint64_t b) {
    asm("fma.rn.f32x2 %0, %1, %2, %0;" : "+l"(c) : "l"(a), "l"(b));
}
__device__ __forceinline__ float2 unpk2(uint64_t v) {
    float2 r;
    asm("mov.b64 {%0, %1}, %2;" : "=f"(r.x), "=f"(r.y) : "l"(v));
    return r;
}

// ---------------- fused hist + x->fp16 (both exactly EE = NN*16 items) --------
__global__ void k_hist_cvtx(const int* __restrict__ dst, const float* __restrict__ x,
                            __half* __restrict__ xh) {
    int i = blockIdx.x * blockDim.x + threadIdx.x;
    if (i < EE) atomicAdd(&g_deg[dst[i]], 1);
    if (i < NN * 16) {
        float2 v = *(const float2*)(x + (size_t)i * 2);
        __half2 h = __floats2half2_rn(v.x, v.y);
        *(__half2*)(xh + (size_t)i * 2) = h;
    }
}

__global__ void k_scan() {
    const int ITEMS = 40;
    int t = threadIdx.x;
    int base = t * ITEMS;
    int sum = 0;
    for (int i = 0; i < ITEMS; i++) {
        int idx = base + i;
        if (idx < NN) sum += g_deg[idx];
    }
    __shared__ int wsum[32];
    int lane = t & 31, wid = t >> 5;
    int v = sum;
    #pragma unroll
    for (int o = 1; o < 32; o <<= 1) {
        int u = __shfl_up_sync(0xffffffffu, v, o);
        if (lane >= o) v += u;
    }
    if (lane == 31) wsum[wid] = v;
    __syncthreads();
    if (wid == 0) {
        int w = wsum[lane];
        #pragma unroll
        for (int o = 1; o < 32; o <<= 1) {
            int u = __shfl_up_sync(0xffffffffu, w, o);
            if (lane >= o) w += u;
        }
        wsum[lane] = w;
    }
    __syncthreads();
    int excl = v - sum + (wid > 0 ? wsum[wid - 1] : 0);
    int run = excl;
    for (int i = 0; i < ITEMS; i++) {
        int idx = base + i;
        if (idx < NN) { g_off[idx] = run; g_cur[idx] = run; run += g_deg[idx]; }
    }
    if (t == 1023) g_off[NN] = EE;
}

// ---------------- fp16 HMMA GEMM body + fused logits (device fn) ----------------
template <int K>
__device__ void gemm_body(const __half* __restrict__ in, const float* __restrict__ W,
                          __half2* __restrict__ h16, const float* __restrict__ as_,
                          const float* __restrict__ ad_, int blk) {
    constexpr int CH = K / 32;
    __shared__ __half As[2][128][40];
    __shared__ __half Ws[2][32][136];

    int t = threadIdx.x;
    int lane = t & 31;
    int warp = t >> 5;
    int warpM = warp & 1;
    int warpN = warp >> 1;
    int row0 = blk * 128;

    float acc[4][4][4];
    #pragma unroll
    for (int mt = 0; mt < 4; mt++)
        #pragma unroll
        for (int nt = 0; nt < 4; nt++)
            #pragma unroll
            for (int r = 0; r < 4; r++) acc[mt][nt][r] = 0.f;

    float4 wreg[4];

    {
        #pragma unroll
        for (int j = 0; j < 2; j++) {
            int slot = t + j * 256;
            int r = slot >> 2, k8 = (slot & 3) * 8;
            int rg = row0 + r; if (rg >= NN) rg = NN - 1;
            cpasync16(smem_u32(&As[0][r][k8]), in + (size_t)rg * K + k8);
        }
        #pragma unroll
        for (int j = 0; j < 4; j++) {
            int slot = t + j * 256;
            int kk = slot >> 5, c4 = (slot & 31) * 4;
            float4 v = *(const float4*)(W + (size_t)kk * 128 + c4);
            __half2 h0 = __floats2half2_rn(v.x, v.y);
            __half2 h1 = __floats2half2_rn(v.z, v.w);
            uint2 p = {*(uint32_t*)&h0, *(uint32_t*)&h1};
            *(uint2*)&Ws[0][kk][c4] = p;
        }
        asm volatile("cp.async.commit_group;");
        asm volatile("cp.async.wait_group 0;");
        __syncthreads();
    }

    for (int c = 0; c < CH; c++) {
        int cur = c & 1, nxt = cur ^ 1;
        bool more = (c + 1 < CH);
        if (more) {
            int k0 = (c + 1) * 32;
            #pragma unroll
            for (int j = 0; j < 2; j++) {
                int slot = t + j * 256;
                int r = slot >> 2, k8 = (slot & 3) * 8;
                int rg = row0 + r; if (rg >= NN) rg = NN - 1;
                cpasync16(smem_u32(&As[nxt][r][k8]), in + (size_t)rg * K + k0 + k8);
            }
            asm volatile("cp.async.commit_group;");
            #pragma unroll
            for (int j = 0; j < 4; j++) {
                int slot = t + j * 256;
                int kk = slot >> 5, c4 = (slot & 31) * 4;
                wreg[j] = *(const float4*)(W + (size_t)(k0 + kk) * 128 + c4);
            }
        }

        #pragma unroll
        for (int ks = 0; ks < 2; ks++) {
            uint32_t a[4][4], b[4][2];
            #pragma unroll
            for (int mt = 0; mt < 4; mt++) {
                int r = warpM * 64 + mt * 16 + (lane & 15);
                uint32_t addr = smem_u32(&As[cur][r][ks * 16 + ((lane >> 4) * 8)]);
                asm volatile("ldmatrix.sync.aligned.m8n8.x4.shared.b16 {%0,%1,%2,%3}, [%4];"
                    : "=r"(a[mt][0]), "=r"(a[mt][1]), "=r"(a[mt][2]), "=r"(a[mt][3])
                    : "r"(addr));
            }
            #pragma unroll
            for (int nt = 0; nt < 4; nt++) {
                int kk = ks * 16 + (lane & 15);
                uint32_t addr = smem_u32(&Ws[cur][kk][warpN * 32 + nt * 8]);
                asm volatile("ldmatrix.sync.aligned.m8n8.x2.trans.shared.b16 {%0,%1}, [%2];"
                    : "=r"(b[nt][0]), "=r"(b[nt][1]) : "r"(addr));
            }
            #pragma unroll
            for (int mt = 0; mt < 4; mt++)
                #pragma unroll
                for (int nt = 0; nt < 4; nt++)
                    asm volatile(
                        "mma.sync.aligned.m16n8k16.row.col.f32.f16.f16.f32 "
                        "{%0,%1,%2,%3}, {%4,%5,%6,%7}, {%8,%9}, {%0,%1,%2,%3};"
                        : "+f"(acc[mt][nt][0]), "+f"(acc[mt][nt][1]),
                          "+f"(acc[mt][nt][2]), "+f"(acc[mt][nt][3])
                        : "r"(a[mt][0]), "r"(a[mt][1]), "r"(a[mt][2]), "r"(a[mt][3]),
                          "r"(b[nt][0]), "r"(b[nt][1]));
        }

        if (more) {
            #pragma unroll
            for (int j = 0; j < 4; j++) {
                int slot = t + j * 256;
                int kk = slot >> 5, c4 = (slot & 31) * 4;
                __half2 h0 = __floats2half2_rn(wreg[j].x, wreg[j].y);
                __half2 h1 = __floats2half2_rn(wreg[j].z, wreg[j].w);
                uint2 p = {*(uint32_t*)&h0, *(uint32_t*)&h1};
                *(uint2*)&Ws[nxt][kk][c4] = p;
            }
            asm volatile("cp.async.wait_group 0;");
        }
        __syncthreads();
    }

    // ---- epilogue: fp16 h store + fused fp32 logits ----
    int hbase = warpN * 2;
    float asv[4][2], adv[4][2];
    #pragma unroll
    for (int nt = 0; nt < 4; nt++) {
        int col = warpN * 32 + nt * 8 + (lane & 3) * 2;
        int hh = col >> 4;
        int lc = col & 15;
        asv[nt][0] = __ldg(as_ + hh * 16 + lc);
        asv[nt][1] = __ldg(as_ + hh * 16 + lc + 1);
        adv[nt][0] = __ldg(ad_ + hh * 16 + lc);
        adv[nt][1] = __ldg(ad_ + hh * 16 + lc + 1);
    }
    #pragma unroll
    for (int mt = 0; mt < 4; mt++) {
        int r0 = row0 + warpM * 64 + mt * 16 + (lane >> 2);
        float sA[2] = {0.f, 0.f}, dA[2] = {0.f, 0.f};
        float sB[2] = {0.f, 0.f}, dB[2] = {0.f, 0.f};
        #pragma unroll
        for (int nt = 0; nt < 4; nt++) {
            int hs = nt >> 1;
            sA[hs] += acc[mt][nt][0] * asv[nt][0] + acc[mt][nt][1] * asv[nt][1];
            dA[hs] += acc[mt][nt][0] * adv[nt][0] + acc[mt][nt][1] * adv[nt][1];
            sB[hs] += acc[mt][nt][2] * asv[nt][0] + acc[mt][nt][3] * asv[nt][1];
            dB[hs] += acc[mt][nt][2] * adv[nt][0] + acc[mt][nt][3] * adv[nt][1];
            __half2 hv0 = __floats2half2_rn(acc[mt][nt][0], acc[mt][nt][1]);
            __half2 hv1 = __floats2half2_rn(acc[mt][nt][2], acc[mt][nt][3]);
            int colh = warpN * 16 + nt * 4 + (lane & 3);
            if (r0 < NN)     h16[(size_t)r0 * 64 + colh] = hv0;
            if (r0 + 8 < NN) h16[(size_t)(r0 + 8) * 64 + colh] = hv1;
        }
        #pragma unroll
        for (int h = 0; h < 2; h++) {
            #pragma unroll
            for (int o = 1; o <= 2; o <<= 1) {
                sA[h] += __shfl_xor_sync(0xffffffffu, sA[h], o);
                dA[h] += __shfl_xor_sync(0xffffffffu, dA[h], o);
                sB[h] += __shfl_xor_sync(0xffffffffu, sB[h], o);
                dB[h] += __shfl_xor_sync(0xffffffffu, dB[h], o);
            }
        }
        if ((lane & 3) == 0) {
            #pragma unroll
            for (int h = 0; h < 2; h++) {
                if (r0 < NN) {
                    g_als[r0 * NH + hbase + h] = sA[h];
                    g_ald[r0 * NH + hbase + h] = dA[h];
                }
                if (r0 + 8 < NN) {
                    g_als[(r0 + 8) * NH + hbase + h] = sB[h];
                    g_ald[(r0 + 8) * NH + hbase + h] = dB[h];
                }
            }
        }
    }
}

template <int K>
__global__ void __launch_bounds__(256) k_gemm_h(const __half* __restrict__ in,
                                                const float* __restrict__ W,
                                                __half2* __restrict__ h16,
                                                const float* __restrict__ as_,
                                                const float* __restrict__ ad_) {
    gemm_body<K>(in, W, h16, as_, ad_, blockIdx.x);
}

// gemm<32> for blocks 0..312, CSR fill for blocks 313..2812 (one launch)
__global__ void __launch_bounds__(256) k_gemm_fill(const __half* __restrict__ in,
                                                   const float* __restrict__ W,
                                                   __half2* __restrict__ h16,
                                                   const float* __restrict__ as_,
                                                   const float* __restrict__ ad_,
                                                   const int* __restrict__ src,
                                                   const int* __restrict__ dst) {
    if (blockIdx.x < 313) {
        gemm_body<32>(in, W, h16, as_, ad_, blockIdx.x);
    } else {
        int i = (blockIdx.x - 313) * blockDim.x + threadIdx.x;
        if (i < EE) {
            int p = atomicAdd(&g_cur[dst[i]], 1);
            g_csr[p] = src[i];
        }
    }
}

// ---------------- agg: single-sweep softmax (no max-shift) — exact R14 body ----
__global__ void k_agg(const __half2* __restrict__ h, const float* __restrict__ bias,
                      __half2* __restrict__ outf) {
    int warp = (blockIdx.x * blockDim.x + threadIdx.x) >> 5;
    if (warp >= NN) return;
    int lane = threadIdx.x & 31;
    int node = warp;
    int beg = g_off[node], end = g_off[node + 1];
    int head3 = lane >> 2;
    float aldh = g_ald[node * NH + head3];

    float4 acc;
    float d;
    {
        float w = __expf(lrelu(g_als[node * NH + head3] + aldh));
        uint2 raw = *(const uint2*)(h + (size_t)node * 64 + lane * 2);
        float2 c0 = __half22float2(*(__half2*)&raw.x);
        float2 c1 = __half22float2(*(__half2*)&raw.y);
        acc.x = w * c0.x; acc.y = w * c0.y; acc.z = w * c1.x; acc.w = w * c1.y;
        d = w;
    }
    int e = beg;
    for (; e + 3 < end; e += 4) {
        int s0 = g_csr[e], s1 = g_csr[e + 1], s2 = g_csr[e + 2], s3 = g_csr[e + 3];
        float l0 = g_als[s0 * NH + head3];
        float l1 = g_als[s1 * NH + head3];
        float l2 = g_als[s2 * NH + head3];
        float l3 = g_als[s3 * NH + head3];
        uint2 r0 = *(const uint2*)(h + (size_t)s0 * 64 + lane * 2);
        uint2 r1 = *(const uint2*)(h + (size_t)s1 * 64 + lane * 2);
        uint2 r2 = *(const uint2*)(h + (size_t)s2 * 64 + lane * 2);
        uint2 r3 = *(const uint2*)(h + (size_t)s3 * 64 + lane * 2);
        float w0 = __expf(lrelu(l0 + aldh));
        float w1 = __expf(lrelu(l1 + aldh));
        float w2 = __expf(lrelu(l2 + aldh));
        float w3 = __expf(lrelu(l3 + aldh));
        d += (w0 + w1) + (w2 + w3);
        float2 h00 = __half22float2(*(__half2*)&r0.x);
        float2 h01 = __half22float2(*(__half2*)&r0.y);
        float2 h10 = __half22float2(*(__half2*)&r1.x);
        float2 h11 = __half22float2(*(__half2*)&r1.y);
        float2 h20 = __half22float2(*(__half2*)&r2.x);
        float2 h21 = __half22float2(*(__half2*)&r2.y);
        float2 h30 = __half22float2(*(__half2*)&r3.x);
        float2 h31 = __half22float2(*(__half2*)&r3.y);
        acc.x += w0 * h00.x + w1 * h10.x + w2 * h20.x + w3 * h30.x;
        acc.y += w0 * h00.y + w1 * h10.y + w2 * h20.y + w3 * h30.y;
        acc.z += w0 * h01.x + w1 * h11.x + w2 * h21.x + w3 * h31.x;
        acc.w += w0 * h01.y + w1 * h11.y + w2 * h21.y + w3 * h31.y;
    }
    for (; e < end; e++) {
        int s0 = g_csr[e];
        float w = __expf(lrelu(g_als[s0 * NH + head3] + aldh));
        uint2 raw = *(const uint2*)(h + (size_t)s0 * 64 + lane * 2);
        float2 c0 = __half22float2(*(__half2*)&raw.x);
        float2 c1 = __half22float2(*(__half2*)&raw.y);
        d += w;
        acc.x += w * c0.x; acc.y += w * c0.y; acc.z += w * c1.x; acc.w += w * c1.y;
    }
    float inv = 1.f / d;
    float4 bv = *(const float4*)(bias + lane * 4);
    float ox = fmaxf(acc.x * inv + bv.x, 0.f);
    float oy = fmaxf(acc.y * inv + bv.y, 0.f);
    float oz = fmaxf(acc.z * inv + bv.z, 0.f);
    float ow = fmaxf(acc.w * inv + bv.w, 0.f);
    __half2 q0 = __floats2half2_rn(ox, oy);
    __half2 q1 = __floats2half2_rn(oz, ow);
    uint2 st = {*(uint32_t*)&q0, *(uint32_t*)&q1};
    *(uint2*)(outf + (size_t)node * 64 + lane * 2) = st;
}

// ---------------- fused tail: pool + fc128 + fc256 + head (block = 8 graphs) ----
__device__ __forceinline__ int lower_bound_i(const int* __restrict__ a, int n, int key) {
    int lo = 0, hi = n;
    while (lo < hi) {
        int mid = (lo + hi) >> 1;
        if (a[mid] < key) lo = mid + 1; else hi = mid;
    }
    return lo;
}

__global__ void __launch_bounds__(256) k_tail(const __half2* __restrict__ feat,
                                              const int* __restrict__ batch,
                                              const float* __restrict__ fW0,
                                              const float* __restrict__ fb0,
                                              const float* __restrict__ fW1,
                                              const float* __restrict__ fb1,
                                              const float* __restrict__ oW,
                                              const float* __restrict__ ob,
                                              float* __restrict__ out) {
    __shared__ float2 spool[4][HC];    // graph pair j holds graphs (2j, 2j+1)
    __shared__ float2 sm0[4][MM];
    __shared__ float2 sm1[4][MM];
    int t = threadIdx.x;
    int warp = t >> 5, lane = t & 31;
    int gblk = blockIdx.x * 8;

    // pool: warp per graph
    {
        int g = gblk + warp;
        int start = lower_bound_i(batch, NN, g);
        int end = lower_bound_i(batch, NN, g + 1);
        float4 acc = {0.f, 0.f, 0.f, 0.f};
        for (int n = start; n < end; n++) {
            uint2 raw = *(const uint2*)(feat + (size_t)n * 64 + lane * 2);
            float2 c0 = __half22float2(*(__half2*)&raw.x);
            float2 c1 = __half22float2(*(__half2*)&raw.y);
            acc.x += c0.x; acc.y += c0.y; acc.z += c1.x; acc.w += c1.y;
        }
        float invc = (end > start) ? 1.f / (float)(end - start) : 0.f;
        int p = warp >> 1, s = warp & 1;
        ((float*)&spool[p][lane * 4 + 0])[s] = acc.x * invc;
        ((float*)&spool[p][lane * 4 + 1])[s] = acc.y * invc;
        ((float*)&spool[p][lane * 4 + 2])[s] = acc.z * invc;
        ((float*)&spool[p][lane * 4 + 3])[s] = acc.w * invc;
    }
    __syncthreads();

    // fc1: K=128 -> 256, t = output channel
    {
        uint64_t a[4] = {0ull, 0ull, 0ull, 0ull};
        for (int k = 0; k < HC; k++) {
            float w = fW0[(size_t)k * MM + t];
            uint64_t w2 = pk2(w, w);
            #pragma unroll
            for (int j = 0; j < 4; j++) fma2(a[j], w2, *(const uint64_t*)&spool[j][k]);
        }
        float bb = fb0[t];
        #pragma unroll
        for (int j = 0; j < 4; j++) {
            float2 p = unpk2(a[j]);
            sm0[j][t] = make_float2(fmaxf(p.x + bb, 0.f), fmaxf(p.y + bb, 0.f));
        }
    }
    __syncthreads();

    // fc2: K=256 -> 256
    {
        uint64_t a[4] = {0ull, 0ull, 0ull, 0ull};
        for (int k = 0; k < MM; k++) {
            float w = fW1[(size_t)k * MM + t];
            uint64_t w2 = pk2(w, w);
            #pragma unroll
            for (int j = 0; j < 4; j++) fma2(a[j], w2, *(const uint64_t*)&sm0[j][k]);
        }
        float bb = fb1[t];
        #pragma unroll
        for (int j = 0; j < 4; j++) {
            float2 p = unpk2(a[j]);
            sm1[j][t] = make_float2(fmaxf(p.x + bb, 0.f), fmaxf(p.y + bb, 0.f));
        }
    }
    __syncthreads();

    // head: warp per graph
    {
        int g = gblk + warp;
        int p = warp >> 1, s = warp & 1;
        float a0 = 0.f, a1 = 0.f;
        for (int k = lane; k < MM; k += 32) {
            float v = ((const float*)&sm1[p][k])[s];
            a0 += v * oW[k * 2];
            a1 += v * oW[k * 2 + 1];
        }
        #pragma unroll
        for (int o = 16; o > 0; o >>= 1) {
            a0 += __shfl_xor_sync(0xffffffffu, a0, o);
            a1 += __shfl_xor_sync(0xffffffffu, a1, o);
        }
        if (lane == 0) {
            out[g * 2] = a0 + ob[0];
            out[g * 2 + 1] = a1 + ob[1];
        }
    }
}

// ---------------- launch ----------------
extern "C" void kernel_launch(void* const* d_in, const int* in_sizes, int n_in,
                              void* d_out, int out_size) {
    const float* x     = (const float*)d_in[0];
    const int*   ei    = (const int*)d_in[1];
    const int*   batch = (const int*)d_in[2];
    const float* W0  = (const float*)d_in[3];
    const float* b0  = (const float*)d_in[4];
    const float* as0 = (const float*)d_in[5];
    const float* ad0 = (const float*)d_in[6];
    const float* W1  = (const float*)d_in[7];
    const float* b1  = (const float*)d_in[8];
    const float* as1 = (const float*)d_in[9];
    const float* ad1 = (const float*)d_in[10];
    const float* W2  = (const float*)d_in[11];
    const float* b2  = (const float*)d_in[12];
    const float* as2 = (const float*)d_in[13];
    const float* ad2 = (const float*)d_in[14];
    const float* fW0 = (const float*)d_in[15];
    const float* fb0 = (const float*)d_in[16];
    const float* fW1 = (const float*)d_in[17];
    const float* fb1 = (const float*)d_in[18];
    const float* oW  = (const float*)d_in[19];
    const float* ob  = (const float*)d_in[20];
    float* out = (float*)d_out;

    const int* src = ei;
    const int* dst = ei + EE;

    __half* p_x16;
    __half2 *p_h16, *p_fA, *p_fB;
    cudaGetSymbolAddress((void**)&p_x16, g_x16);
    cudaGetSymbolAddress((void**)&p_h16, g_h16);
    cudaGetSymbolAddress((void**)&p_fA, g_fA16);
    cudaGetSymbolAddress((void**)&p_fB, g_fB16);
    int* p_deg;
    cudaGetSymbolAddress((void**)&p_deg, g_deg);

    const int GEMM_GRID = (NN + 127) / 128;   // 313
    const int AGG_GRID = (NN + 7) / 8;

    cudaMemsetAsync(p_deg, 0, NN * sizeof(int));

    // launch 1: hist + x->fp16
    k_hist_cvtx<<<(EE + 255) / 256, 256>>>(dst, x, p_x16);
    // launch 2: scan (off + cur)
    k_scan<<<1, 1024>>>();
    // launch 3: gemm<32> + CSR fill
    k_gemm_fill<<<313 + (EE + 255) / 256, 256>>>(p_x16, W0, p_h16, as0, ad0, src, dst);
    // launch 4 (PROFILED): layer-0 agg
    k_agg<<<AGG_GRID, 256>>>(p_h16, b0, p_fA);
    // layer 1
    k_gemm_h<128><<<GEMM_GRID, 256>>>((const __half*)p_fA, W1, p_h16, as1, ad1);
    k_agg<<<AGG_GRID, 256>>>(p_h16, b1, p_fB);
    // layer 2
    k_gemm_h<128><<<GEMM_GRID, 256>>>((const __half*)p_fB, W2, p_h16, as2, ad2);
    k_agg<<<AGG_GRID, 256>>>(p_h16, b2, p_fA);

    // fused tail: pool + fc + fc + head
    k_tail<<<GG / 8, 256>>>(p_fA, batch, fW0, fb0, fW1, fb1, oW, ob, out);
}

// round 17
// speedup vs baseline: 1.6019x; 1.0180x over previous
#include <cuda_runtime.h>
#include <cuda_fp16.h>
#include <cstddef>
#include <cstdint>

#define NN 40000
#define EE 640000
#define GG 1000
#define HC 128
#define NH 8
#define CC 16
#define MM 256

// ---------------- scratch (static device globals; no allocation) ----------------
__device__ __half  g_x16[NN * 32];    // fp16 copy of input x
__device__ __half2 g_h16[NN * 64];    // fp16 pre-agg features (gather source)
__device__ __half2 g_fA16[NN * 64];   // fp16 post-agg features (ping)
__device__ __half2 g_fB16[NN * 64];   // fp16 post-agg features (pong)
__device__ float g_als[NN * NH];
__device__ float g_ald[NN * NH];
__device__ int   g_deg[NN];
__device__ int   g_cur[NN];
__device__ int   g_off[NN + 1];
__device__ int   g_csr[EE];

__device__ __forceinline__ float lrelu(float x) { return x > 0.f ? x : 0.2f * x; }

__device__ __forceinline__ uint32_t smem_u32(const void* p) {
    uint32_t a;
    asm("{ .reg .u64 t; cvta.to.shared.u64 t, %1; cvt.u32.u64 %0, t; }"
        : "=r"(a) : "l"(p));
    return a;
}

__device__ __forceinline__ void cpasync16(uint32_t s, const void* g) {
    asm volatile("cp.async.ca.shared.global [%0], [%1], 16;" :: "r"(s), "l"(g));
}

// ---- packed f32x2 ----
__device__ __forceinline__ uint64_t pk2(float lo, float hi) {
    uint64_t r;
    asm("mov.b64 %0, {%1, %2};" : "=l"(r) : "f"(lo), "f"(hi));
    return r;
}
__device__ __forceinline__ void fma2(uint64_t& c, uint64_t a, uint64_t b) {
    asm("fma.rn.f32x2 %0, %1, %2, %0;" : "+l"(c) : "l"(a), "l"(b));
}
__device__ __forceinline__ float2 unpk2(uint64_t v) {
    float2 r;
    asm("mov.b64 {%0, %1}, %2;" : "=f"(r.x), "=f"(r.y) : "l"(v));
    return r;
}

// ---------------- fused hist + x->fp16 (both exactly EE = NN*16 items) --------
__global__ void k_hist_cvtx(const int* __restrict__ dst, const float* __restrict__ x,
                            __half* __restrict__ xh) {
    int i = blockIdx.x * blockDim.x + threadIdx.x;
    if (i < EE) atomicAdd(&g_deg[dst[i]], 1);
    if (i < NN * 16) {
        float2 v = *(const float2*)(x + (size_t)i * 2);
        __half2 h = __floats2half2_rn(v.x, v.y);
        *(__half2*)(xh + (size_t)i * 2) = h;
    }
}

__global__ void k_scan() {
    const int ITEMS = 40;
    int t = threadIdx.x;
    int base = t * ITEMS;
    int sum = 0;
    for (int i = 0; i < ITEMS; i++) {
        int idx = base + i;
        if (idx < NN) sum += g_deg[idx];
    }
    __shared__ int wsum[32];
    int lane = t & 31, wid = t >> 5;
    int v = sum;
    #pragma unroll
    for (int o = 1; o < 32; o <<= 1) {
        int u = __shfl_up_sync(0xffffffffu, v, o);
        if (lane >= o) v += u;
    }
    if (lane == 31) wsum[wid] = v;
    __syncthreads();
    if (wid == 0) {
        int w = wsum[lane];
        #pragma unroll
        for (int o = 1; o < 32; o <<= 1) {
            int u = __shfl_up_sync(0xffffffffu, w, o);
            if (lane >= o) w += u;
        }
        wsum[lane] = w;
    }
    __syncthreads();
    int excl = v - sum + (wid > 0 ? wsum[wid - 1] : 0);
    int run = excl;
    for (int i = 0; i < ITEMS; i++) {
        int idx = base + i;
        if (idx < NN) { g_off[idx] = run; g_cur[idx] = run; run += g_deg[idx]; }
    }
    if (t == 1023) g_off[NN] = EE;
}

// ---------------- fp16 HMMA GEMM body + fused logits (device fn) ----------------
template <int K>
__device__ void gemm_body(const __half* __restrict__ in, const float* __restrict__ W,
                          __half2* __restrict__ h16, const float* __restrict__ as_,
                          const float* __restrict__ ad_, int blk) {
    constexpr int CH = K / 32;
    __shared__ __half As[2][128][40];
    __shared__ __half Ws[2][32][136];

    int t = threadIdx.x;
    int lane = t & 31;
    int warp = t >> 5;
    int warpM = warp & 1;
    int warpN = warp >> 1;
    int row0 = blk * 128;

    float acc[4][4][4];
    #pragma unroll
    for (int mt = 0; mt < 4; mt++)
        #pragma unroll
        for (int nt = 0; nt < 4; nt++)
            #pragma unroll
            for (int r = 0; r < 4; r++) acc[mt][nt][r] = 0.f;

    float4 wreg[4];

    {
        #pragma unroll
        for (int j = 0; j < 2; j++) {
            int slot = t + j * 256;
            int r = slot >> 2, k8 = (slot & 3) * 8;
            int rg = row0 + r; if (rg >= NN) rg = NN - 1;
            cpasync16(smem_u32(&As[0][r][k8]), in + (size_t)rg * K + k8);
        }
        #pragma unroll
        for (int j = 0; j < 4; j++) {
            int slot = t + j * 256;
            int kk = slot >> 5, c4 = (slot & 31) * 4;
            float4 v = *(const float4*)(W + (size_t)kk * 128 + c4);
            __half2 h0 = __floats2half2_rn(v.x, v.y);
            __half2 h1 = __floats2half2_rn(v.z, v.w);
            uint2 p = {*(uint32_t*)&h0, *(uint32_t*)&h1};
            *(uint2*)&Ws[0][kk][c4] = p;
        }
        asm volatile("cp.async.commit_group;");
        asm volatile("cp.async.wait_group 0;");
        __syncthreads();
    }

    for (int c = 0; c < CH; c++) {
        int cur = c & 1, nxt = cur ^ 1;
        bool more = (c + 1 < CH);
        if (more) {
            int k0 = (c + 1) * 32;
            #pragma unroll
            for (int j = 0; j < 2; j++) {
                int slot = t + j * 256;
                int r = slot >> 2, k8 = (slot & 3) * 8;
                int rg = row0 + r; if (rg >= NN) rg = NN - 1;
                cpasync16(smem_u32(&As[nxt][r][k8]), in + (size_t)rg * K + k0 + k8);
            }
            asm volatile("cp.async.commit_group;");
            #pragma unroll
            for (int j = 0; j < 4; j++) {
                int slot = t + j * 256;
                int kk = slot >> 5, c4 = (slot & 31) * 4;
                wreg[j] = *(const float4*)(W + (size_t)(k0 + kk) * 128 + c4);
            }
        }

        #pragma unroll
        for (int ks = 0; ks < 2; ks++) {
            uint32_t a[4][4], b[4][2];
            #pragma unroll
            for (int mt = 0; mt < 4; mt++) {
                int r = warpM * 64 + mt * 16 + (lane & 15);
                uint32_t addr = smem_u32(&As[cur][r][ks * 16 + ((lane >> 4) * 8)]);
                asm volatile("ldmatrix.sync.aligned.m8n8.x4.shared.b16 {%0,%1,%2,%3}, [%4];"
                    : "=r"(a[mt][0]), "=r"(a[mt][1]), "=r"(a[mt][2]), "=r"(a[mt][3])
                    : "r"(addr));
            }
            #pragma unroll
            for (int nt = 0; nt < 4; nt++) {
                int kk = ks * 16 + (lane & 15);
                uint32_t addr = smem_u32(&Ws[cur][kk][warpN * 32 + nt * 8]);
                asm volatile("ldmatrix.sync.aligned.m8n8.x2.trans.shared.b16 {%0,%1}, [%2];"
                    : "=r"(b[nt][0]), "=r"(b[nt][1]) : "r"(addr));
            }
            #pragma unroll
            for (int mt = 0; mt < 4; mt++)
                #pragma unroll
                for (int nt = 0; nt < 4; nt++)
                    asm volatile(
                        "mma.sync.aligned.m16n8k16.row.col.f32.f16.f16.f32 "
                        "{%0,%1,%2,%3}, {%4,%5,%6,%7}, {%8,%9}, {%0,%1,%2,%3};"
                        : "+f"(acc[mt][nt][0]), "+f"(acc[mt][nt][1]),
                          "+f"(acc[mt][nt][2]), "+f"(acc[mt][nt][3])
                        : "r"(a[mt][0]), "r"(a[mt][1]), "r"(a[mt][2]), "r"(a[mt][3]),
                          "r"(b[nt][0]), "r"(b[nt][1]));
        }

        if (more) {
            #pragma unroll
            for (int j = 0; j < 4; j++) {
                int slot = t + j * 256;
                int kk = slot >> 5, c4 = (slot & 31) * 4;
                __half2 h0 = __floats2half2_rn(wreg[j].x, wreg[j].y);
                __half2 h1 = __floats2half2_rn(wreg[j].z, wreg[j].w);
                uint2 p = {*(uint32_t*)&h0, *(uint32_t*)&h1};
                *(uint2*)&Ws[nxt][kk][c4] = p;
            }
            asm volatile("cp.async.wait_group 0;");
        }
        __syncthreads();
    }

    // ---- epilogue: fp16 h store + fused fp32 logits ----
    int hbase = warpN * 2;
    float asv[4][2], adv[4][2];
    #pragma unroll
    for (int nt = 0; nt < 4; nt++) {
        int col = warpN * 32 + nt * 8 + (lane & 3) * 2;
        int hh = col >> 4;
        int lc = col & 15;
        asv[nt][0] = __ldg(as_ + hh * 16 + lc);
        asv[nt][1] = __ldg(as_ + hh * 16 + lc + 1);
        adv[nt][0] = __ldg(ad_ + hh * 16 + lc);
        adv[nt][1] = __ldg(ad_ + hh * 16 + lc + 1);
    }
    #pragma unroll
    for (int mt = 0; mt < 4; mt++) {
        int r0 = row0 + warpM * 64 + mt * 16 + (lane >> 2);
        float sA[2] = {0.f, 0.f}, dA[2] = {0.f, 0.f};
        float sB[2] = {0.f, 0.f}, dB[2] = {0.f, 0.f};
        #pragma unroll
        for (int nt = 0; nt < 4; nt++) {
            int hs = nt >> 1;
            sA[hs] += acc[mt][nt][0] * asv[nt][0] + acc[mt][nt][1] * asv[nt][1];
            dA[hs] += acc[mt][nt][0] * adv[nt][0] + acc[mt][nt][1] * adv[nt][1];
            sB[hs] += acc[mt][nt][2] * asv[nt][0] + acc[mt][nt][3] * asv[nt][1];
            dB[hs] += acc[mt][nt][2] * adv[nt][0] + acc[mt][nt][3] * adv[nt][1];
            __half2 hv0 = __floats2half2_rn(acc[mt][nt][0], acc[mt][nt][1]);
            __half2 hv1 = __floats2half2_rn(acc[mt][nt][2], acc[mt][nt][3]);
            int colh = warpN * 16 + nt * 4 + (lane & 3);
            if (r0 < NN)     h16[(size_t)r0 * 64 + colh] = hv0;
            if (r0 + 8 < NN) h16[(size_t)(r0 + 8) * 64 + colh] = hv1;
        }
        #pragma unroll
        for (int h = 0; h < 2; h++) {
            #pragma unroll
            for (int o = 1; o <= 2; o <<= 1) {
                sA[h] += __shfl_xor_sync(0xffffffffu, sA[h], o);
                dA[h] += __shfl_xor_sync(0xffffffffu, dA[h], o);
                sB[h] += __shfl_xor_sync(0xffffffffu, sB[h], o);
                dB[h] += __shfl_xor_sync(0xffffffffu, dB[h], o);
            }
        }
        if ((lane & 3) == 0) {
            #pragma unroll
            for (int h = 0; h < 2; h++) {
                if (r0 < NN) {
                    g_als[r0 * NH + hbase + h] = sA[h];
                    g_ald[r0 * NH + hbase + h] = dA[h];
                }
                if (r0 + 8 < NN) {
                    g_als[(r0 + 8) * NH + hbase + h] = sB[h];
                    g_ald[(r0 + 8) * NH + hbase + h] = dB[h];
                }
            }
        }
    }
}

template <int K>
__global__ void __launch_bounds__(256) k_gemm_h(const __half* __restrict__ in,
                                                const float* __restrict__ W,
                                                __half2* __restrict__ h16,
                                                const float* __restrict__ as_,
                                                const float* __restrict__ ad_) {
    gemm_body<K>(in, W, h16, as_, ad_, blockIdx.x);
}

// gemm<32> for blocks 0..312, CSR fill for blocks 313..2812 (one launch)
__global__ void __launch_bounds__(256) k_gemm_fill(const __half* __restrict__ in,
                                                   const float* __restrict__ W,
                                                   __half2* __restrict__ h16,
                                                   const float* __restrict__ as_,
                                                   const float* __restrict__ ad_,
                                                   const int* __restrict__ src,
                                                   const int* __restrict__ dst) {
    if (blockIdx.x < 313) {
        gemm_body<32>(in, W, h16, as_, ad_, blockIdx.x);
    } else {
        int i = (blockIdx.x - 313) * blockDim.x + threadIdx.x;
        if (i < EE) {
            int p = atomicAdd(&g_cur[dst[i]], 1);
            g_csr[p] = src[i];
        }
    }
}

// ---------------- agg: half-warp-per-edge single-sweep softmax ------------------
// 16 lanes per edge item (uint4 = 8 channels/lane); two items per warp instr.
// item 0 = self loop (half 0), item i>=1 = edge beg+i-1. Halves combined at end.
__global__ void k_agg(const __half2* __restrict__ h, const float* __restrict__ bias,
                      __half2* __restrict__ outf) {
    int warp = (blockIdx.x * blockDim.x + threadIdx.x) >> 5;
    if (warp >= NN) return;
    int lane = threadIdx.x & 31;
    int half = lane >> 4;
    int lh = lane & 15;
    int head = lh >> 1;
    int node = warp;
    int beg = g_off[node], end = g_off[node + 1];
    int total = 1 + end - beg;
    float aldh = g_ald[node * NH + head];
    const uint4* hb = (const uint4*)h;     // 16 uint4 per node row

    float a0 = 0.f, a1 = 0.f, a2 = 0.f, a3 = 0.f;
    float a4 = 0.f, a5 = 0.f, a6 = 0.f, a7 = 0.f;
    float d = 0.f;
    for (int it = half; it < total; it += 2) {
        int ei = beg + it - 1;
        int s = (it == 0) ? node : g_csr[ei < 0 ? 0 : ei];
        float l = g_als[s * NH + head];
        float w = __expf(lrelu(l + aldh));
        d += w;
        uint4 raw = hb[s * 16 + lh];
        float2 c0 = __half22float2(*(__half2*)&raw.x);
        float2 c1 = __half22float2(*(__half2*)&raw.y);
        float2 c2 = __half22float2(*(__half2*)&raw.z);
        float2 c3 = __half22float2(*(__half2*)&raw.w);
        a0 += w * c0.x; a1 += w * c0.y; a2 += w * c1.x; a3 += w * c1.y;
        a4 += w * c2.x; a5 += w * c2.y; a6 += w * c3.x; a7 += w * c3.y;
    }
    d  += __shfl_xor_sync(0xffffffffu, d,  16);
    a0 += __shfl_xor_sync(0xffffffffu, a0, 16);
    a1 += __shfl_xor_sync(0xffffffffu, a1, 16);
    a2 += __shfl_xor_sync(0xffffffffu, a2, 16);
    a3 += __shfl_xor_sync(0xffffffffu, a3, 16);
    a4 += __shfl_xor_sync(0xffffffffu, a4, 16);
    a5 += __shfl_xor_sync(0xffffffffu, a5, 16);
    a6 += __shfl_xor_sync(0xffffffffu, a6, 16);
    a7 += __shfl_xor_sync(0xffffffffu, a7, 16);
    if (half == 0) {
        float inv = 1.f / d;
        float4 b0 = *(const float4*)(bias + lh * 8);
        float4 b1 = *(const float4*)(bias + lh * 8 + 4);
        float o0 = fmaxf(a0 * inv + b0.x, 0.f);
        float o1 = fmaxf(a1 * inv + b0.y, 0.f);
        float o2 = fmaxf(a2 * inv + b0.z, 0.f);
        float o3 = fmaxf(a3 * inv + b0.w, 0.f);
        float o4 = fmaxf(a4 * inv + b1.x, 0.f);
        float o5 = fmaxf(a5 * inv + b1.y, 0.f);
        float o6 = fmaxf(a6 * inv + b1.z, 0.f);
        float o7 = fmaxf(a7 * inv + b1.w, 0.f);
        __half2 q0 = __floats2half2_rn(o0, o1);
        __half2 q1 = __floats2half2_rn(o2, o3);
        __half2 q2 = __floats2half2_rn(o4, o5);
        __half2 q3 = __floats2half2_rn(o6, o7);
        uint4 st = {*(uint32_t*)&q0, *(uint32_t*)&q1, *(uint32_t*)&q2, *(uint32_t*)&q3};
        ((uint4*)outf)[node * 16 + lh] = st;
    }
}

// ---------------- fused tail: pool + fc128 + fc256 + head (block = 8 graphs) ----
__device__ __forceinline__ int lower_bound_i(const int* __restrict__ a, int n, int key) {
    int lo = 0, hi = n;
    while (lo < hi) {
        int mid = (lo + hi) >> 1;
        if (a[mid] < key) lo = mid + 1; else hi = mid;
    }
    return lo;
}

__global__ void __launch_bounds__(256) k_tail(const __half2* __restrict__ feat,
                                              const int* __restrict__ batch,
                                              const float* __restrict__ fW0,
                                              const float* __restrict__ fb0,
                                              const float* __restrict__ fW1,
                                              const float* __restrict__ fb1,
                                              const float* __restrict__ oW,
                                              const float* __restrict__ ob,
                                              float* __restrict__ out) {
    __shared__ float2 spool[4][HC];
    __shared__ float2 sm0[4][MM];
    __shared__ float2 sm1[4][MM];
    int t = threadIdx.x;
    int warp = t >> 5, lane = t & 31;
    int gblk = blockIdx.x * 8;

    {
        int g = gblk + warp;
        int start = lower_bound_i(batch, NN, g);
        int end = lower_bound_i(batch, NN, g + 1);
        float4 acc = {0.f, 0.f, 0.f, 0.f};
        for (int n = start; n < end; n++) {
            uint2 raw = *(const uint2*)(feat + (size_t)n * 64 + lane * 2);
            float2 c0 = __half22float2(*(__half2*)&raw.x);
            float2 c1 = __half22float2(*(__half2*)&raw.y);
            acc.x += c0.x; acc.y += c0.y; acc.z += c1.x; acc.w += c1.y;
        }
        float invc = (end > start) ? 1.f / (float)(end - start) : 0.f;
        int p = warp >> 1, s = warp & 1;
        ((float*)&spool[p][lane * 4 + 0])[s] = acc.x * invc;
        ((float*)&spool[p][lane * 4 + 1])[s] = acc.y * invc;
        ((float*)&spool[p][lane * 4 + 2])[s] = acc.z * invc;
        ((float*)&spool[p][lane * 4 + 3])[s] = acc.w * invc;
    }
    __syncthreads();

    {
        uint64_t a[4] = {0ull, 0ull, 0ull, 0ull};
        for (int k = 0; k < HC; k++) {
            float w = fW0[(size_t)k * MM + t];
            uint64_t w2 = pk2(w, w);
            #pragma unroll
            for (int j = 0; j < 4; j++) fma2(a[j], w2, *(const uint64_t*)&spool[j][k]);
        }
        float bb = fb0[t];
        #pragma unroll
        for (int j = 0; j < 4; j++) {
            float2 p = unpk2(a[j]);
            sm0[j][t] = make_float2(fmaxf(p.x + bb, 0.f), fmaxf(p.y + bb, 0.f));
        }
    }
    __syncthreads();

    {
        uint64_t a[4] = {0ull, 0ull, 0ull, 0ull};
        for (int k = 0; k < MM; k++) {
            float w = fW1[(size_t)k * MM + t];
            uint64_t w2 = pk2(w, w);
            #pragma unroll
            for (int j = 0; j < 4; j++) fma2(a[j], w2, *(const uint64_t*)&sm0[j][k]);
        }
        float bb = fb1[t];
        #pragma unroll
        for (int j = 0; j < 4; j++) {
            float2 p = unpk2(a[j]);
            sm1[j][t] = make_float2(fmaxf(p.x + bb, 0.f), fmaxf(p.y + bb, 0.f));
        }
    }
    __syncthreads();

    {
        int g = gblk + warp;
        int p = warp >> 1, s = warp & 1;
        float a0 = 0.f, a1 = 0.f;
        for (int k = lane; k < MM; k += 32) {
            float v = ((const float*)&sm1[p][k])[s];
            a0 += v * oW[k * 2];
            a1 += v * oW[k * 2 + 1];
        }
        #pragma unroll
        for (int o = 16; o > 0; o >>= 1) {
            a0 += __shfl_xor_sync(0xffffffffu, a0, o);
            a1 += __shfl_xor_sync(0xffffffffu, a1, o);
        }
        if (lane == 0) {
            out[g * 2] = a0 + ob[0];
            out[g * 2 + 1] = a1 + ob[1];
        }
    }
}

// ---------------- launch ----------------
extern "C" void kernel_launch(void* const* d_in, const int* in_sizes, int n_in,
                              void* d_out, int out_size) {
    const float* x     = (const float*)d_in[0];
    const int*   ei    = (const int*)d_in[1];
    const int*   batch = (const int*)d_in[2];
    const float* W0  = (const float*)d_in[3];
    const float* b0  = (const float*)d_in[4];
    const float* as0 = (const float*)d_in[5];
    const float* ad0 = (const float*)d_in[6];
    const float* W1  = (const float*)d_in[7];
    const float* b1  = (const float*)d_in[8];
    const float* as1 = (const float*)d_in[9];
    const float* ad1 = (const float*)d_in[10];
    const float* W2  = (const float*)d_in[11];
    const float* b2  = (const float*)d_in[12];
    const float* as2 = (const float*)d_in[13];
    const float* ad2 = (const float*)d_in[14];
    const float* fW0 = (const float*)d_in[15];
    const float* fb0 = (const float*)d_in[16];
    const float* fW1 = (const float*)d_in[17];
    const float* fb1 = (const float*)d_in[18];
    const float* oW  = (const float*)d_in[19];
    const float* ob  = (const float*)d_in[20];
    float* out = (float*)d_out;

    const int* src = ei;
    const int* dst = ei + EE;

    __half* p_x16;
    __half2 *p_h16, *p_fA, *p_fB;
    cudaGetSymbolAddress((void**)&p_x16, g_x16);
    cudaGetSymbolAddress((void**)&p_h16, g_h16);
    cudaGetSymbolAddress((void**)&p_fA, g_fA16);
    cudaGetSymbolAddress((void**)&p_fB, g_fB16);
    int* p_deg;
    cudaGetSymbolAddress((void**)&p_deg, g_deg);

    const int GEMM_GRID = (NN + 127) / 128;   // 313
    const int AGG_GRID = (NN + 7) / 8;

    cudaMemsetAsync(p_deg, 0, NN * sizeof(int));

    // launch 1: hist + x->fp16
    k_hist_cvtx<<<(EE + 255) / 256, 256>>>(dst, x, p_x16);
    // launch 2: scan (off + cur)
    k_scan<<<1, 1024>>>();
    // launch 3: gemm<32> + CSR fill
    k_gemm_fill<<<313 + (EE + 255) / 256, 256>>>(p_x16, W0, p_h16, as0, ad0, src, dst);
    // launch 4 (PROFILED): layer-0 agg
    k_agg<<<AGG_GRID, 256>>>(p_h16, b0, p_fA);
    // layer 1
    k_gemm_h<128><<<GEMM_GRID, 256>>>((const __half*)p_fA, W1, p_h16, as1, ad1);
    k_agg<<<AGG_GRID, 256>>>(p_h16, b1, p_fB);
    // layer 2
    k_gemm_h<128><<<GEMM_GRID, 256>>>((const __half*)p_fB, W2, p_h16, as2, ad2);
    k_agg<<<AGG_GRID, 256>>>(p_h16, b2, p_fA);

    // fused tail: pool + fc + fc + head
    k_tail<<<GG / 8, 256>>>(p_fA, batch, fW0, fb0, fW1, fb1, oW, ob, out);
}